// round 13
// baseline (speedup 1.0000x reference)
#include <cuda_runtime.h>
#include <cstdint>

// ---------------------------------------------------------------------------
// local_graph_creator: adj = relu(tanh(3*(vec1@gEmb.T - gEmb@vec1.T))),
// per-row top-20 (value desc, index asc) binary mask applied.
//
// Exact-output structure (rel_err == 0.0 across rounds 1-12): each output row
// is zeros plus satval at the 20 smallest column indices whose tanh saturates
// (bits == satval). Only an exact N x 256 strip of scores is needed; rows
// with <20 saturated strip entries go to an exact full-row fallback.
//
// Round-12 model update: the big zero runs at 5.38 TB/s (61.3us, measured);
// cross-stream "overlap" never materialized (zero's 10000 warps monopolize
// the SMs). So: single-stream serial pipeline, and kill the real remaining
// fat -- prep was LDG-bound (1024 global loads/thread). prep now stages the
// gathered emb rows + fc1_w in smem; the dot product is pure conflict-free
// LDS with the SAME k-ascending fmaf chain (bit-identical vec1).
//
//   default stream: zero_tailcols -> prep -> strip -> finish -> fallback
// ---------------------------------------------------------------------------

#define MAX_NPAD 10112
#define STRIPW 256

__device__ float g_Xt[128 * MAX_NPAD];     // [k][i]  X = [vec1 | -gEmb]
__device__ float g_Yt[128 * MAX_NPAD];     // [k][i]  Y = [gEmb  |  vec1]
__device__ unsigned g_maskS[MAX_NPAD * 8]; // strip tie bitmask (256 cols/row)
__device__ int g_fb_cnt;
__device__ int g_fb_list[MAX_NPAD];

__device__ __forceinline__ float tanh_xla(float x) {
    const float kClamp = 7.99881172180175781f;
    float ax = fabsf(x);
    float xc = fminf(fmaxf(x, -kClamp), kClamp);
    float x2 = xc * xc;
    float p = -2.76076847742355e-16f;
    p = fmaf(x2, p, 2.00018790482477e-13f);
    p = fmaf(x2, p, -8.60467152213735e-11f);
    p = fmaf(x2, p, 5.12229709037114e-08f);
    p = fmaf(x2, p, 1.48572235717979e-05f);
    p = fmaf(x2, p, 6.37261928875436e-04f);
    p = fmaf(x2, p, 4.89352455891786e-03f);
    p = xc * p;
    float q = fmaf(x2, 1.19825839466702e-06f, 1.18534705686654e-04f);
    q = fmaf(x2, q, 2.26843463243900e-03f);
    q = fmaf(x2, q, 4.89352518554385e-03f);
    float r = p / q;
    return (ax < 0.0004f) ? x : r;
}

__device__ __forceinline__ float sat_val() { return tanh_xla(8.0f); }

__device__ __forceinline__ void cp_async16(uint32_t saddr, const void* gaddr) {
    asm volatile("cp.async.cg.shared.global [%0], [%1], 16;" ::
                 "r"(saddr), "l"(gaddr));
}

// ---------------------------------------------------------------------------
// zero_tailcols: measured 5.38 TB/s writer (warp per row, 8 rows/CTA, plain
// float4), restricted to cols [STRIPW, N).
// ---------------------------------------------------------------------------
__global__ __launch_bounds__(256) void zero_tailcols_kernel(
    float* __restrict__ out, int N) {
    const int row = blockIdx.x * 8 + (threadIdx.x >> 5);
    const int lane = threadIdx.x & 31;
    if (row >= N) return;
    if (N <= STRIPW) return;
    float* rowp = out + (size_t)row * N + STRIPW;
    const int len = N - STRIPW;  // floats to zero
    const int nv = len >> 2;
    const float4 z = make_float4(0.0f, 0.0f, 0.0f, 0.0f);
    for (int q = lane; q < nv; q += 32) reinterpret_cast<float4*>(rowp)[q] = z;
    for (int q = nv * 4 + lane; q < len; q += 32) rowp[q] = 0.0f;
}

// ---------------------------------------------------------------------------
// prep: 64 rows per block, ALL-SMEM dot product.
//   dynamic smem: wst[64][65] = fc1_w rows, sv[64][65] = vec1^T,
//                 sbuf[64][65] = gathered emb rows, then gEmb^T; bs; sidx.
// Same k-ascending fmaf chain as all prior rounds -> bit-identical vec1.
// ---------------------------------------------------------------------------
#define PREP_SMEM_FLOATS (3 * 4160 + 64 + 64)
__global__ __launch_bounds__(256) void prep_kernel(
    const int* __restrict__ idx, const float* __restrict__ gEmb,
    const float* __restrict__ embW, const float* __restrict__ fc1w,
    const float* __restrict__ fc1b, int N, int npad) {
    extern __shared__ float ps[];
    float* wst = ps;             // [d][k] stride 65 (fc1w row-major copy)
    float* sv = ps + 4160;       // [d][il] stride 65
    float* sbuf = ps + 8320;     // [il][k] emb rows; later [d][il] gEmb
    float* bs = ps + 12480;      // [64]
    int* sidx = (int*)(ps + 12544);  // [64]

    const int t = threadIdx.x;
    const int bi0 = blockIdx.x * 64;

    if (blockIdx.x == 0 && t == 0) g_fb_cnt = 0;

    if (t < 64) {
        bs[t] = fc1b[t];
        int i = bi0 + t;
        sidx[t] = (i < N) ? idx[i] : 0;
    }
    // wst[d][k] = fc1w[d*64+k]  (coalesced read, conflict-free write)
    for (int e = t; e < 64 * 64; e += 256) {
        int d = e >> 6, k = e & 63;
        wst[d * 65 + k] = fc1w[e];
    }
    __syncthreads();

    // gathered emb rows into smem (coalesced over k)
    for (int e = t; e < 64 * 64; e += 256) {
        int il = e >> 6, k = e & 63;
        int i = bi0 + il;
        sbuf[il * 65 + k] = (i < N) ? embW[(size_t)sidx[il] * 64 + k] : 0.0f;
    }
    __syncthreads();

    // vec1: thread (rq, d); er broadcast LDS, wst stride-1 LDS
    const int d = t & 63;
    const int rq = t >> 6;
#pragma unroll
    for (int rr = 0; rr < 16; rr++) {
        int il = rr * 4 + rq;
        int i = bi0 + il;
        float v = 0.0f;
        if (i < N) {
            const float* er = &sbuf[il * 65];
            const float* wr = &wst[d * 65];
            float acc = 0.0f;
#pragma unroll
            for (int k = 0; k < 64; k++) acc = fmaf(er[k], wr[k], acc);
            acc += bs[d];
            v = tanh_xla(3.0f * acc);
        }
        sv[d * 65 + il] = v;
    }
    __syncthreads();

    // reuse sbuf as gEmb^T [d][il] (conflict-free: (d*65+il)%32 distinct)
#pragma unroll 4
    for (int e = t; e < 64 * 64; e += 256) {
        int il = e >> 6, dd = e & 63;
        int i = bi0 + il;
        sbuf[dd * 65 + il] = (i < N) ? gEmb[(size_t)i * 64 + dd] : 0.0f;
    }
    __syncthreads();

    // coalesced float4 packing of Xt/Yt
#pragma unroll
    for (int p = 0; p < 8; p++) {
        int e = p * 256 + t;
        int dd = e >> 4;
        int i4 = (e & 15) * 4;
        float4 xv, yv;
        if (dd < 64) {
            xv.x = sv[dd * 65 + i4 + 0]; xv.y = sv[dd * 65 + i4 + 1];
            xv.z = sv[dd * 65 + i4 + 2]; xv.w = sv[dd * 65 + i4 + 3];
            yv.x = sbuf[dd * 65 + i4 + 0]; yv.y = sbuf[dd * 65 + i4 + 1];
            yv.z = sbuf[dd * 65 + i4 + 2]; yv.w = sbuf[dd * 65 + i4 + 3];
        } else {
            int dl = dd - 64;
            xv.x = -sbuf[dl * 65 + i4 + 0]; xv.y = -sbuf[dl * 65 + i4 + 1];
            xv.z = -sbuf[dl * 65 + i4 + 2]; xv.w = -sbuf[dl * 65 + i4 + 3];
            yv.x = sv[dl * 65 + i4 + 0];  yv.y = sv[dl * 65 + i4 + 1];
            yv.z = sv[dl * 65 + i4 + 2];  yv.w = sv[dl * 65 + i4 + 3];
        }
        *(float4*)&g_Xt[(size_t)dd * npad + bi0 + i4] = xv;
        *(float4*)&g_Yt[(size_t)dd * npad + bi0 + i4] = yv;
    }
}

// ---------------------------------------------------------------------------
// strip: 64 rows x 128 cols per CTA, grid (2, npad/64). Whole K=128 in smem.
// Per-element k-ascending fp32 fmaf chain, bit-identical to prior rounds.
// Emits saturation bitmask words (cols bn..bn+127 -> words (bn>>5)..+3).
// ---------------------------------------------------------------------------
__global__ __launch_bounds__(256, 2) void strip_kernel(int npad) {
    const int bm = blockIdx.y * 64;
    const int bn = blockIdx.x * 128;

    extern __shared__ float sm[];
    float* Asf = sm;           // [k][r] 128 x 64
    float* Bsf = sm + 8192;    // [k][r] 128 x 128

    const int t = threadIdx.x;
    const int tx = t & 15, ty = t >> 4;

    {
        const float4* Xv = reinterpret_cast<const float4*>(g_Xt);
        const float4* Yv = reinterpret_cast<const float4*>(g_Yt);
        uint32_t As_s = (uint32_t)__cvta_generic_to_shared(Asf);
        uint32_t Bs_s = (uint32_t)__cvta_generic_to_shared(Bsf);
        const int np4 = npad >> 2;
        const int bm4 = bm >> 2, bn4 = bn >> 2;
#pragma unroll
        for (int e = 0; e < 8; e++) {
            int q = e * 256 + t;      // 0..2047
            int k = q >> 4;           // 0..127
            int r4 = q & 15;
            cp_async16(As_s + q * 16, &Xv[(size_t)k * np4 + bm4 + r4]);
        }
#pragma unroll
        for (int e = 0; e < 16; e++) {
            int q = e * 256 + t;      // 0..4095
            int k = q >> 5;
            int r4 = q & 31;
            cp_async16(Bs_s + q * 16, &Yv[(size_t)k * np4 + bn4 + r4]);
        }
        asm volatile("cp.async.commit_group;");
        asm volatile("cp.async.wait_group 0;");
    }
    __syncthreads();

    float acc[4][8];
#pragma unroll
    for (int i = 0; i < 4; i++)
#pragma unroll
        for (int j = 0; j < 8; j++) acc[i][j] = 0.0f;

#pragma unroll 4
    for (int k = 0; k < 128; k++) {
        const float* ak = Asf + k * 64;
        const float* bk = Bsf + k * 128;
        float4 a0 = *(const float4*)(ak + ty * 4);
        float4 b0 = *(const float4*)(bk + tx * 4);
        float4 b1 = *(const float4*)(bk + 64 + tx * 4);
        float ra[4] = {a0.x, a0.y, a0.z, a0.w};
        float rb[8] = {b0.x, b0.y, b0.z, b0.w, b1.x, b1.y, b1.z, b1.w};
#pragma unroll
        for (int i = 0; i < 4; i++)
#pragma unroll
            for (int j = 0; j < 8; j++)
                acc[i][j] = fmaf(ra[i], rb[j], acc[i][j]);
    }

#pragma unroll
    for (int i = 0; i < 4; i++)
#pragma unroll
        for (int j = 0; j < 8; j++) acc[i][j] = tanh_xla(3.0f * acc[i][j]);

    __syncthreads();  // As/Bs dead

    unsigned* mUw = reinterpret_cast<unsigned*>(sm);  // [64][32] nibbles
    const unsigned satb = __float_as_uint(sat_val());

#pragma unroll
    for (int ii = 0; ii < 4; ii++) {
        int r = ty * 4 + ii;
#pragma unroll
        for (int q = 0; q < 2; q++) {
            unsigned nib = 0;
#pragma unroll
            for (int b = 0; b < 4; b++)
                nib |= (__float_as_uint(acc[ii][q * 4 + b]) == satb) << b;
            mUw[r * 32 + 16 * q + tx] = nib;
        }
    }
    __syncthreads();

    {
        int r = t >> 2, ww = t & 3;
        unsigned wd = 0;
#pragma unroll
        for (int b = 0; b < 8; b++) wd |= mUw[r * 32 + ww * 8 + b] << (4 * b);
        g_maskS[(size_t)(bm + r) * 8 + (bn >> 5) + ww] = wd;
    }
}

// ---------------------------------------------------------------------------
// finish: warp per row. Zero cols [0, min(STRIPW,N)), then scatter satval at
// the 20 smallest set bits of the strip mask. <20 bits -> fallback list.
// ---------------------------------------------------------------------------
__global__ __launch_bounds__(256) void finish_kernel(float* __restrict__ out,
                                                     int N) {
    const int row = blockIdx.x * 8 + (threadIdx.x >> 5);
    const int lane = threadIdx.x & 31;
    if (row >= N) return;

    float* rowp = out + (size_t)row * N;
    const int head = (N < STRIPW) ? N : STRIPW;
    {
        const int nv = head >> 2;
        const float4 z = make_float4(0.0f, 0.0f, 0.0f, 0.0f);
        for (int q = lane; q < nv; q += 32)
            reinterpret_cast<float4*>(rowp)[q] = z;
        for (int q = nv * 4 + lane; q < head; q += 32) rowp[q] = 0.0f;
    }
    __syncwarp();

    unsigned w = (lane < 8) ? g_maskS[(size_t)row * 8 + lane] : 0u;
    int c = __popc(w);
    int incl = c;
#pragma unroll
    for (int s = 1; s < 32; s <<= 1) {
        int o = __shfl_up_sync(0xffffffffu, incl, s);
        if (lane >= s) incl += o;
    }
    int excl = incl - c;
    int total = __shfl_sync(0xffffffffu, incl, 31);

    if (total >= 20) {
        const float sv = sat_val();
        int base = excl;
        unsigned ww = w;
        while (ww && base < 20) {
            int b = __ffs(ww) - 1;
            ww &= ww - 1;
            rowp[lane * 32 + b] = sv;
            base++;
        }
    } else if (lane == 0) {
        int p = atomicAdd(&g_fb_cnt, 1);
        g_fb_list[p] = row;
    }
}

// ---------------------------------------------------------------------------
// fallback: exact full-row recompute + general top-20 (expected 0 rows).
// ---------------------------------------------------------------------------
__global__ __launch_bounds__(256) void fallback_kernel(float* __restrict__ out,
                                                       int N, int npad) {
    __shared__ float sX[128];
    __shared__ __align__(16) float srow[10016];
    __shared__ unsigned long long red[256];
    __shared__ int selIdx[20];
    __shared__ float selVal[20];

    const int t = threadIdx.x;
    const int cnt = g_fb_cnt;

    for (int ri = blockIdx.x; ri < cnt; ri += gridDim.x) {
        const int row = g_fb_list[ri];
        if (t < 128) sX[t] = g_Xt[(size_t)t * npad + row];
        __syncthreads();

        for (int j = t; j < N; j += 256) {
            float a = 0.0f;
#pragma unroll 4
            for (int k = 0; k < 128; k++)
                a = fmaf(sX[k], g_Yt[(size_t)k * npad + j], a);
            srow[j] = fmaxf(tanh_xla(3.0f * a), 0.0f);
        }
        __syncthreads();

        unsigned long long cand[20];
#pragma unroll
        for (int c = 0; c < 20; c++) cand[c] = 0ull;
        unsigned long long curMin = 0ull;
        for (int q = t; q < N; q += 256) {
            unsigned vb = __float_as_uint(srow[q]);
            if (vb == 0x80000000u) vb = 0u;
            unsigned long long key =
                ((unsigned long long)vb << 32) |
                (unsigned long long)(0xFFFFFFFFu - (unsigned)q);
            if (key > curMin) {
                bool done = false;
#pragma unroll
                for (int c = 0; c < 20; c++) {
                    if (!done && cand[c] == curMin) {
                        cand[c] = key;
                        done = true;
                    }
                }
                unsigned long long m = cand[0];
#pragma unroll
                for (int c = 1; c < 20; c++) m = (cand[c] < m) ? cand[c] : m;
                curMin = m;
            }
        }
        for (int it = 0; it < 20; it++) {
            unsigned long long m = cand[0];
#pragma unroll
            for (int c = 1; c < 20; c++) m = (cand[c] > m) ? cand[c] : m;
            red[t] = m;
            __syncthreads();
            for (int s = 128; s >= 32; s >>= 1) {
                if (t < s) {
                    unsigned long long o = red[t + s];
                    if (o > red[t]) red[t] = o;
                }
                __syncthreads();
            }
            if (t < 32) {
                unsigned long long g = red[t];
#pragma unroll
                for (int s = 16; s; s >>= 1) {
                    unsigned long long o = __shfl_xor_sync(0xffffffffu, g, s);
                    if (o > g) g = o;
                }
                if (t == 0) red[0] = g;
            }
            __syncthreads();
            unsigned long long g = red[0];
            if (t == 0) {
                if (g != 0ull) {
                    selIdx[it] =
                        (int)(0xFFFFFFFFu - (unsigned)(g & 0xFFFFFFFFull));
                    selVal[it] = __uint_as_float((unsigned)(g >> 32));
                } else {
                    selIdx[it] = 0;
                    selVal[it] = 0.0f;
                }
            }
            if (g != 0ull) {
#pragma unroll
                for (int c = 0; c < 20; c++)
                    if (cand[c] == g) cand[c] = 0ull;
            }
            __syncthreads();
        }
        if (t < 20) out[(size_t)row * N + selIdx[t]] = selVal[t];
        __syncthreads();
    }
}

// ---------------------------------------------------------------------------
extern "C" void kernel_launch(void* const* d_in, const int* in_sizes, int n_in,
                              void* d_out, int out_size) {
    const int* idx = (const int*)d_in[0];
    const float* gEmb = (const float*)d_in[1];
    const float* embW = (const float*)d_in[2];
    const float* fc1w = (const float*)d_in[3];
    const float* fc1b = (const float*)d_in[4];
    float* out = (float*)d_out;

    int N = in_sizes[0];
    int npad = ((N + 127) / 128) * 128;
    int tiles64 = npad / 64;

    static bool s_init = false;
    if (!s_init) {
        cudaFuncSetAttribute(strip_kernel,
                             cudaFuncAttributeMaxDynamicSharedMemorySize,
                             98304);
        cudaFuncSetAttribute(prep_kernel,
                             cudaFuncAttributeMaxDynamicSharedMemorySize,
                             PREP_SMEM_FLOATS * 4);
        s_init = true;
    }

    // single-stream serial pipeline (overlap was shown not to materialize)
    zero_tailcols_kernel<<<(N + 7) / 8, 256>>>(out, N);
    prep_kernel<<<npad / 64, 256, PREP_SMEM_FLOATS * 4>>>(idx, gEmb, embW,
                                                          fc1w, fc1b, N, npad);
    strip_kernel<<<dim3(2, tiles64), 256, 98304>>>(npad);
    finish_kernel<<<(N + 7) / 8, 256>>>(out, N);
    fallback_kernel<<<16, 256>>>(out, N, npad);
}

// round 14
// speedup vs baseline: 1.1109x; 1.1109x over previous
#include <cuda_runtime.h>
#include <cstdint>

// ---------------------------------------------------------------------------
// local_graph_creator: adj = relu(tanh(3*(vec1@gEmb.T - gEmb@vec1.T))),
// per-row top-20 (value desc, index asc) binary mask applied.
//
// Exact-output structure (rel_err == 0.0 across rounds 1-13): each output row
// is zeros plus satval at the 20 smallest column indices whose tanh saturates
// (bits == satval). Only an exact N x 256 strip of scores is needed; rows
// with <20 saturated strip entries go to an exact full-row fallback.
//
// Round-13 finding: overlap never happened in rounds 9-12 because the zero's
// 1250 CTAs fill every SM's warp slots (8 CTAs/SM), so concurrent kernels
// queue. Fix: cap the zero at 296 CTAs (2/SM via launch_bounds), each warp
// looping rows with stride 2368 (row-contiguous 40KB walks preserved ->
// 5.4 TB/s locality), leaving 6 CTA slots + all smem per SM for the fork
// chain to genuinely co-run.
//
//   main stream:  zero_capped (296 CTAs, cols 256..N) --+-> fallback
//   fork stream:  prep -> strip -> finish (cols 0..256)-+   (join via event)
// ---------------------------------------------------------------------------

#define MAX_NPAD 10112
#define STRIPW 256

__device__ float g_Xt[128 * MAX_NPAD];     // [k][i]  X = [vec1 | -gEmb]
__device__ float g_Yt[128 * MAX_NPAD];     // [k][i]  Y = [gEmb  |  vec1]
__device__ unsigned g_maskS[MAX_NPAD * 8]; // strip tie bitmask (256 cols/row)
__device__ int g_fb_cnt;
__device__ int g_fb_list[MAX_NPAD];

__device__ __forceinline__ float tanh_xla(float x) {
    const float kClamp = 7.99881172180175781f;
    float ax = fabsf(x);
    float xc = fminf(fmaxf(x, -kClamp), kClamp);
    float x2 = xc * xc;
    float p = -2.76076847742355e-16f;
    p = fmaf(x2, p, 2.00018790482477e-13f);
    p = fmaf(x2, p, -8.60467152213735e-11f);
    p = fmaf(x2, p, 5.12229709037114e-08f);
    p = fmaf(x2, p, 1.48572235717979e-05f);
    p = fmaf(x2, p, 6.37261928875436e-04f);
    p = fmaf(x2, p, 4.89352455891786e-03f);
    p = xc * p;
    float q = fmaf(x2, 1.19825839466702e-06f, 1.18534705686654e-04f);
    q = fmaf(x2, q, 2.26843463243900e-03f);
    q = fmaf(x2, q, 4.89352518554385e-03f);
    float r = p / q;
    return (ax < 0.0004f) ? x : r;
}

__device__ __forceinline__ float sat_val() { return tanh_xla(8.0f); }

__device__ __forceinline__ void cp_async16(uint32_t saddr, const void* gaddr) {
    asm volatile("cp.async.cg.shared.global [%0], [%1], 16;" ::
                 "r"(saddr), "l"(gaddr));
}

// ---------------------------------------------------------------------------
// zero_capped: 296 CTAs (max 2/SM), warp-per-row with row stride 2368.
// Row-contiguous float4 walks (the measured-fast locality), but leaves
// 6 CTA slots + all smem per SM free so fork-stream kernels co-run.
// ---------------------------------------------------------------------------
#define ZCTAS 296
__global__ __launch_bounds__(256, 2) void zero_capped_kernel(
    float* __restrict__ out, int N) {
    const int gw = blockIdx.x * 8 + (threadIdx.x >> 5);  // global warp id
    const int lane = threadIdx.x & 31;
    if (N <= STRIPW) return;
    const int len = N - STRIPW;
    const int nv = len >> 2;
    const float4 z = make_float4(0.0f, 0.0f, 0.0f, 0.0f);
    for (int row = gw; row < N; row += ZCTAS * 8) {
        float* rowp = out + (size_t)row * N + STRIPW;
        for (int q = lane; q < nv; q += 32)
            reinterpret_cast<float4*>(rowp)[q] = z;
        for (int q = nv * 4 + lane; q < len; q += 32) rowp[q] = 0.0f;
    }
}

// ---------------------------------------------------------------------------
// prep: 64 rows per block, ALL-SMEM dot product (bit-identical vec1 chain).
// ---------------------------------------------------------------------------
#define PREP_SMEM_FLOATS (3 * 4160 + 64 + 64)
__global__ __launch_bounds__(256) void prep_kernel(
    const int* __restrict__ idx, const float* __restrict__ gEmb,
    const float* __restrict__ embW, const float* __restrict__ fc1w,
    const float* __restrict__ fc1b, int N, int npad) {
    extern __shared__ float ps[];
    float* wst = ps;             // [d][k] stride 65
    float* sv = ps + 4160;       // [d][il] stride 65
    float* sbuf = ps + 8320;     // [il][k] emb rows; later [d][il] gEmb
    float* bs = ps + 12480;      // [64]
    int* sidx = (int*)(ps + 12544);  // [64]

    const int t = threadIdx.x;
    const int bi0 = blockIdx.x * 64;

    if (blockIdx.x == 0 && t == 0) g_fb_cnt = 0;

    if (t < 64) {
        bs[t] = fc1b[t];
        int i = bi0 + t;
        sidx[t] = (i < N) ? idx[i] : 0;
    }
    for (int e = t; e < 64 * 64; e += 256) {
        int d = e >> 6, k = e & 63;
        wst[d * 65 + k] = fc1w[e];
    }
    __syncthreads();

    for (int e = t; e < 64 * 64; e += 256) {
        int il = e >> 6, k = e & 63;
        int i = bi0 + il;
        sbuf[il * 65 + k] = (i < N) ? embW[(size_t)sidx[il] * 64 + k] : 0.0f;
    }
    __syncthreads();

    const int d = t & 63;
    const int rq = t >> 6;
#pragma unroll
    for (int rr = 0; rr < 16; rr++) {
        int il = rr * 4 + rq;
        int i = bi0 + il;
        float v = 0.0f;
        if (i < N) {
            const float* er = &sbuf[il * 65];
            const float* wr = &wst[d * 65];
            float acc = 0.0f;
#pragma unroll
            for (int k = 0; k < 64; k++) acc = fmaf(er[k], wr[k], acc);
            acc += bs[d];
            v = tanh_xla(3.0f * acc);
        }
        sv[d * 65 + il] = v;
    }
    __syncthreads();

#pragma unroll 4
    for (int e = t; e < 64 * 64; e += 256) {
        int il = e >> 6, dd = e & 63;
        int i = bi0 + il;
        sbuf[dd * 65 + il] = (i < N) ? gEmb[(size_t)i * 64 + dd] : 0.0f;
    }
    __syncthreads();

#pragma unroll
    for (int p = 0; p < 8; p++) {
        int e = p * 256 + t;
        int dd = e >> 4;
        int i4 = (e & 15) * 4;
        float4 xv, yv;
        if (dd < 64) {
            xv.x = sv[dd * 65 + i4 + 0]; xv.y = sv[dd * 65 + i4 + 1];
            xv.z = sv[dd * 65 + i4 + 2]; xv.w = sv[dd * 65 + i4 + 3];
            yv.x = sbuf[dd * 65 + i4 + 0]; yv.y = sbuf[dd * 65 + i4 + 1];
            yv.z = sbuf[dd * 65 + i4 + 2]; yv.w = sbuf[dd * 65 + i4 + 3];
        } else {
            int dl = dd - 64;
            xv.x = -sbuf[dl * 65 + i4 + 0]; xv.y = -sbuf[dl * 65 + i4 + 1];
            xv.z = -sbuf[dl * 65 + i4 + 2]; xv.w = -sbuf[dl * 65 + i4 + 3];
            yv.x = sv[dl * 65 + i4 + 0];  yv.y = sv[dl * 65 + i4 + 1];
            yv.z = sv[dl * 65 + i4 + 2];  yv.w = sv[dl * 65 + i4 + 3];
        }
        *(float4*)&g_Xt[(size_t)dd * npad + bi0 + i4] = xv;
        *(float4*)&g_Yt[(size_t)dd * npad + bi0 + i4] = yv;
    }
}

// ---------------------------------------------------------------------------
// strip: 64 rows x 128 cols per CTA, grid (2, npad/64). Whole K=128 in smem.
// Per-element k-ascending fp32 fmaf chain, bit-identical to prior rounds.
// ---------------------------------------------------------------------------
__global__ __launch_bounds__(256, 2) void strip_kernel(int npad) {
    const int bm = blockIdx.y * 64;
    const int bn = blockIdx.x * 128;

    extern __shared__ float sm[];
    float* Asf = sm;           // [k][r] 128 x 64
    float* Bsf = sm + 8192;    // [k][r] 128 x 128

    const int t = threadIdx.x;
    const int tx = t & 15, ty = t >> 4;

    {
        const float4* Xv = reinterpret_cast<const float4*>(g_Xt);
        const float4* Yv = reinterpret_cast<const float4*>(g_Yt);
        uint32_t As_s = (uint32_t)__cvta_generic_to_shared(Asf);
        uint32_t Bs_s = (uint32_t)__cvta_generic_to_shared(Bsf);
        const int np4 = npad >> 2;
        const int bm4 = bm >> 2, bn4 = bn >> 2;
#pragma unroll
        for (int e = 0; e < 8; e++) {
            int q = e * 256 + t;
            int k = q >> 4;
            int r4 = q & 15;
            cp_async16(As_s + q * 16, &Xv[(size_t)k * np4 + bm4 + r4]);
        }
#pragma unroll
        for (int e = 0; e < 16; e++) {
            int q = e * 256 + t;
            int k = q >> 5;
            int r4 = q & 31;
            cp_async16(Bs_s + q * 16, &Yv[(size_t)k * np4 + bn4 + r4]);
        }
        asm volatile("cp.async.commit_group;");
        asm volatile("cp.async.wait_group 0;");
    }
    __syncthreads();

    float acc[4][8];
#pragma unroll
    for (int i = 0; i < 4; i++)
#pragma unroll
        for (int j = 0; j < 8; j++) acc[i][j] = 0.0f;

#pragma unroll 4
    for (int k = 0; k < 128; k++) {
        const float* ak = Asf + k * 64;
        const float* bk = Bsf + k * 128;
        float4 a0 = *(const float4*)(ak + ty * 4);
        float4 b0 = *(const float4*)(bk + tx * 4);
        float4 b1 = *(const float4*)(bk + 64 + tx * 4);
        float ra[4] = {a0.x, a0.y, a0.z, a0.w};
        float rb[8] = {b0.x, b0.y, b0.z, b0.w, b1.x, b1.y, b1.z, b1.w};
#pragma unroll
        for (int i = 0; i < 4; i++)
#pragma unroll
            for (int j = 0; j < 8; j++)
                acc[i][j] = fmaf(ra[i], rb[j], acc[i][j]);
    }

#pragma unroll
    for (int i = 0; i < 4; i++)
#pragma unroll
        for (int j = 0; j < 8; j++) acc[i][j] = tanh_xla(3.0f * acc[i][j]);

    __syncthreads();  // As/Bs dead

    unsigned* mUw = reinterpret_cast<unsigned*>(sm);  // [64][32] nibbles
    const unsigned satb = __float_as_uint(sat_val());

#pragma unroll
    for (int ii = 0; ii < 4; ii++) {
        int r = ty * 4 + ii;
#pragma unroll
        for (int q = 0; q < 2; q++) {
            unsigned nib = 0;
#pragma unroll
            for (int b = 0; b < 4; b++)
                nib |= (__float_as_uint(acc[ii][q * 4 + b]) == satb) << b;
            mUw[r * 32 + 16 * q + tx] = nib;
        }
    }
    __syncthreads();

    {
        int r = t >> 2, ww = t & 3;
        unsigned wd = 0;
#pragma unroll
        for (int b = 0; b < 8; b++) wd |= mUw[r * 32 + ww * 8 + b] << (4 * b);
        g_maskS[(size_t)(bm + r) * 8 + (bn >> 5) + ww] = wd;
    }
}

// ---------------------------------------------------------------------------
// finish: warp per row. Zero cols [0, min(STRIPW,N)), then scatter satval at
// the 20 smallest set bits of the strip mask. <20 bits -> fallback list.
// ---------------------------------------------------------------------------
__global__ __launch_bounds__(256) void finish_kernel(float* __restrict__ out,
                                                     int N) {
    const int row = blockIdx.x * 8 + (threadIdx.x >> 5);
    const int lane = threadIdx.x & 31;
    if (row >= N) return;

    float* rowp = out + (size_t)row * N;
    const int head = (N < STRIPW) ? N : STRIPW;
    {
        const int nv = head >> 2;
        const float4 z = make_float4(0.0f, 0.0f, 0.0f, 0.0f);
        for (int q = lane; q < nv; q += 32)
            reinterpret_cast<float4*>(rowp)[q] = z;
        for (int q = nv * 4 + lane; q < head; q += 32) rowp[q] = 0.0f;
    }
    __syncwarp();

    unsigned w = (lane < 8) ? g_maskS[(size_t)row * 8 + lane] : 0u;
    int c = __popc(w);
    int incl = c;
#pragma unroll
    for (int s = 1; s < 32; s <<= 1) {
        int o = __shfl_up_sync(0xffffffffu, incl, s);
        if (lane >= s) incl += o;
    }
    int excl = incl - c;
    int total = __shfl_sync(0xffffffffu, incl, 31);

    if (total >= 20) {
        const float sv = sat_val();
        int base = excl;
        unsigned ww = w;
        while (ww && base < 20) {
            int b = __ffs(ww) - 1;
            ww &= ww - 1;
            rowp[lane * 32 + b] = sv;
            base++;
        }
    } else if (lane == 0) {
        int p = atomicAdd(&g_fb_cnt, 1);
        g_fb_list[p] = row;
    }
}

// ---------------------------------------------------------------------------
// fallback: exact full-row recompute + general top-20 (expected 0 rows).
// ---------------------------------------------------------------------------
__global__ __launch_bounds__(256) void fallback_kernel(float* __restrict__ out,
                                                       int N, int npad) {
    __shared__ float sX[128];
    __shared__ __align__(16) float srow[10016];
    __shared__ unsigned long long red[256];
    __shared__ int selIdx[20];
    __shared__ float selVal[20];

    const int t = threadIdx.x;
    const int cnt = g_fb_cnt;

    for (int ri = blockIdx.x; ri < cnt; ri += gridDim.x) {
        const int row = g_fb_list[ri];
        if (t < 128) sX[t] = g_Xt[(size_t)t * npad + row];
        __syncthreads();

        for (int j = t; j < N; j += 256) {
            float a = 0.0f;
#pragma unroll 4
            for (int k = 0; k < 128; k++)
                a = fmaf(sX[k], g_Yt[(size_t)k * npad + j], a);
            srow[j] = fmaxf(tanh_xla(3.0f * a), 0.0f);
        }
        __syncthreads();

        unsigned long long cand[20];
#pragma unroll
        for (int c = 0; c < 20; c++) cand[c] = 0ull;
        unsigned long long curMin = 0ull;
        for (int q = t; q < N; q += 256) {
            unsigned vb = __float_as_uint(srow[q]);
            if (vb == 0x80000000u) vb = 0u;
            unsigned long long key =
                ((unsigned long long)vb << 32) |
                (unsigned long long)(0xFFFFFFFFu - (unsigned)q);
            if (key > curMin) {
                bool done = false;
#pragma unroll
                for (int c = 0; c < 20; c++) {
                    if (!done && cand[c] == curMin) {
                        cand[c] = key;
                        done = true;
                    }
                }
                unsigned long long m = cand[0];
#pragma unroll
                for (int c = 1; c < 20; c++) m = (cand[c] < m) ? cand[c] : m;
                curMin = m;
            }
        }
        for (int it = 0; it < 20; it++) {
            unsigned long long m = cand[0];
#pragma unroll
            for (int c = 1; c < 20; c++) m = (cand[c] > m) ? cand[c] : m;
            red[t] = m;
            __syncthreads();
            for (int s = 128; s >= 32; s >>= 1) {
                if (t < s) {
                    unsigned long long o = red[t + s];
                    if (o > red[t]) red[t] = o;
                }
                __syncthreads();
            }
            if (t < 32) {
                unsigned long long g = red[t];
#pragma unroll
                for (int s = 16; s; s >>= 1) {
                    unsigned long long o = __shfl_xor_sync(0xffffffffu, g, s);
                    if (o > g) g = o;
                }
                if (t == 0) red[0] = g;
            }
            __syncthreads();
            unsigned long long g = red[0];
            if (t == 0) {
                if (g != 0ull) {
                    selIdx[it] =
                        (int)(0xFFFFFFFFu - (unsigned)(g & 0xFFFFFFFFull));
                    selVal[it] = __uint_as_float((unsigned)(g >> 32));
                } else {
                    selIdx[it] = 0;
                    selVal[it] = 0.0f;
                }
            }
            if (g != 0ull) {
#pragma unroll
                for (int c = 0; c < 20; c++)
                    if (cand[c] == g) cand[c] = 0ull;
            }
            __syncthreads();
        }
        if (t < 20) out[(size_t)row * N + selIdx[t]] = selVal[t];
        __syncthreads();
    }
}

// ---------------------------------------------------------------------------
extern "C" void kernel_launch(void* const* d_in, const int* in_sizes, int n_in,
                              void* d_out, int out_size) {
    const int* idx = (const int*)d_in[0];
    const float* gEmb = (const float*)d_in[1];
    const float* embW = (const float*)d_in[2];
    const float* fc1w = (const float*)d_in[3];
    const float* fc1b = (const float*)d_in[4];
    float* out = (float*)d_out;

    int N = in_sizes[0];
    int npad = ((N + 127) / 128) * 128;
    int tiles64 = npad / 64;

    static cudaStream_t s_fork = nullptr;
    static cudaEvent_t s_evFork = nullptr, s_evJoin = nullptr;
    static bool s_init = false;
    if (!s_init) {
        cudaFuncSetAttribute(strip_kernel,
                             cudaFuncAttributeMaxDynamicSharedMemorySize,
                             98304);
        cudaFuncSetAttribute(prep_kernel,
                             cudaFuncAttributeMaxDynamicSharedMemorySize,
                             PREP_SMEM_FLOATS * 4);
        cudaStreamCreateWithFlags(&s_fork, cudaStreamNonBlocking);
        cudaEventCreateWithFlags(&s_evFork, cudaEventDisableTiming);
        cudaEventCreateWithFlags(&s_evJoin, cudaEventDisableTiming);
        s_init = true;
    }

    // fork: prep -> strip -> finish (cols [0,256) + scatter)
    cudaEventRecord(s_evFork, 0);
    cudaStreamWaitEvent(s_fork, s_evFork, 0);
    prep_kernel<<<npad / 64, 256, PREP_SMEM_FLOATS * 4, s_fork>>>(
        idx, gEmb, embW, fc1w, fc1b, N, npad);
    strip_kernel<<<dim3(2, tiles64), 256, 98304, s_fork>>>(npad);
    finish_kernel<<<(N + 7) / 8, 256, 0, s_fork>>>(out, N);
    cudaEventRecord(s_evJoin, s_fork);

    // main: capped-occupancy zero of cols [256, N) — leaves SM room so the
    // fork chain genuinely co-runs
    zero_capped_kernel<<<ZCTAS, 256>>>(out, N);

    // join: fallback needs the fb list (fork) and the zeroed tail (main)
    cudaStreamWaitEvent(0, s_evJoin, 0);
    fallback_kernel<<<16, 256>>>(out, N, npad);
}

// round 15
// speedup vs baseline: 1.1591x; 1.0434x over previous
#include <cuda_runtime.h>
#include <cstdint>

// ---------------------------------------------------------------------------
// local_graph_creator: adj = relu(tanh(3*(vec1@gEmb.T - gEmb@vec1.T))),
// per-row top-20 (value desc, index asc) binary mask applied.
//
// Exact-output structure (rel_err == 0.0 across rounds 1-14): each output row
// is zeros plus satval at the 20 smallest column indices whose tanh saturates
// (bits == satval). Only an exact N x 256 strip of scores is needed; rows
// with <20 saturated strip entries go to an exact full-row fallback.
//
// Round-14 findings: 2 CTAs/SM suffice for the 6.15 TB/s write wall; stream-
// level overlap stays unreliable. So this round fuses at GRID level: one
// kernel where block role is interleaved -- i%5==2 blocks run the strip GEMM
// (bit-identical body), all others zero full contiguous rows. Co-residency
// of DRAM-bound and FMA-bound CTAs is guaranteed by construction.
//
//   default stream: prep -> fused(zero+strip) -> scatter -> fallback
// ---------------------------------------------------------------------------

#define MAX_NPAD 10112
#define STRIPW 256

__device__ float g_Xt[128 * MAX_NPAD];     // [k][i]  X = [vec1 | -gEmb]
__device__ float g_Yt[128 * MAX_NPAD];     // [k][i]  Y = [gEmb  |  vec1]
__device__ unsigned g_maskS[MAX_NPAD * 8]; // strip tie bitmask (256 cols/row)
__device__ int g_fb_cnt;
__device__ int g_fb_list[MAX_NPAD];

__device__ __forceinline__ float tanh_xla(float x) {
    const float kClamp = 7.99881172180175781f;
    float ax = fabsf(x);
    float xc = fminf(fmaxf(x, -kClamp), kClamp);
    float x2 = xc * xc;
    float p = -2.76076847742355e-16f;
    p = fmaf(x2, p, 2.00018790482477e-13f);
    p = fmaf(x2, p, -8.60467152213735e-11f);
    p = fmaf(x2, p, 5.12229709037114e-08f);
    p = fmaf(x2, p, 1.48572235717979e-05f);
    p = fmaf(x2, p, 6.37261928875436e-04f);
    p = fmaf(x2, p, 4.89352455891786e-03f);
    p = xc * p;
    float q = fmaf(x2, 1.19825839466702e-06f, 1.18534705686654e-04f);
    q = fmaf(x2, q, 2.26843463243900e-03f);
    q = fmaf(x2, q, 4.89352518554385e-03f);
    float r = p / q;
    return (ax < 0.0004f) ? x : r;
}

__device__ __forceinline__ float sat_val() { return tanh_xla(8.0f); }

__device__ __forceinline__ void cp_async16(uint32_t saddr, const void* gaddr) {
    asm volatile("cp.async.cg.shared.global [%0], [%1], 16;" ::
                 "r"(saddr), "l"(gaddr));
}

// ---------------------------------------------------------------------------
// prep: 64 rows per block, ALL-SMEM dot product (bit-identical vec1 chain).
// ---------------------------------------------------------------------------
#define PREP_SMEM_FLOATS (3 * 4160 + 64 + 64)
__global__ __launch_bounds__(256) void prep_kernel(
    const int* __restrict__ idx, const float* __restrict__ gEmb,
    const float* __restrict__ embW, const float* __restrict__ fc1w,
    const float* __restrict__ fc1b, int N, int npad) {
    extern __shared__ float ps[];
    float* wst = ps;             // [d][k] stride 65
    float* sv = ps + 4160;       // [d][il] stride 65
    float* sbuf = ps + 8320;     // [il][k] emb rows; later [d][il] gEmb
    float* bs = ps + 12480;      // [64]
    int* sidx = (int*)(ps + 12544);  // [64]

    const int t = threadIdx.x;
    const int bi0 = blockIdx.x * 64;

    if (blockIdx.x == 0 && t == 0) g_fb_cnt = 0;

    if (t < 64) {
        bs[t] = fc1b[t];
        int i = bi0 + t;
        sidx[t] = (i < N) ? idx[i] : 0;
    }
    for (int e = t; e < 64 * 64; e += 256) {
        int d = e >> 6, k = e & 63;
        wst[d * 65 + k] = fc1w[e];
    }
    __syncthreads();

    for (int e = t; e < 64 * 64; e += 256) {
        int il = e >> 6, k = e & 63;
        int i = bi0 + il;
        sbuf[il * 65 + k] = (i < N) ? embW[(size_t)sidx[il] * 64 + k] : 0.0f;
    }
    __syncthreads();

    const int d = t & 63;
    const int rq = t >> 6;
#pragma unroll
    for (int rr = 0; rr < 16; rr++) {
        int il = rr * 4 + rq;
        int i = bi0 + il;
        float v = 0.0f;
        if (i < N) {
            const float* er = &sbuf[il * 65];
            const float* wr = &wst[d * 65];
            float acc = 0.0f;
#pragma unroll
            for (int k = 0; k < 64; k++) acc = fmaf(er[k], wr[k], acc);
            acc += bs[d];
            v = tanh_xla(3.0f * acc);
        }
        sv[d * 65 + il] = v;
    }
    __syncthreads();

#pragma unroll 4
    for (int e = t; e < 64 * 64; e += 256) {
        int il = e >> 6, dd = e & 63;
        int i = bi0 + il;
        sbuf[dd * 65 + il] = (i < N) ? gEmb[(size_t)i * 64 + dd] : 0.0f;
    }
    __syncthreads();

#pragma unroll
    for (int p = 0; p < 8; p++) {
        int e = p * 256 + t;
        int dd = e >> 4;
        int i4 = (e & 15) * 4;
        float4 xv, yv;
        if (dd < 64) {
            xv.x = sv[dd * 65 + i4 + 0]; xv.y = sv[dd * 65 + i4 + 1];
            xv.z = sv[dd * 65 + i4 + 2]; xv.w = sv[dd * 65 + i4 + 3];
            yv.x = sbuf[dd * 65 + i4 + 0]; yv.y = sbuf[dd * 65 + i4 + 1];
            yv.z = sbuf[dd * 65 + i4 + 2]; yv.w = sbuf[dd * 65 + i4 + 3];
        } else {
            int dl = dd - 64;
            xv.x = -sbuf[dl * 65 + i4 + 0]; xv.y = -sbuf[dl * 65 + i4 + 1];
            xv.z = -sbuf[dl * 65 + i4 + 2]; xv.w = -sbuf[dl * 65 + i4 + 3];
            yv.x = sv[dl * 65 + i4 + 0];  yv.y = sv[dl * 65 + i4 + 1];
            yv.z = sv[dl * 65 + i4 + 2];  yv.w = sv[dl * 65 + i4 + 3];
        }
        *(float4*)&g_Xt[(size_t)dd * npad + bi0 + i4] = xv;
        *(float4*)&g_Yt[(size_t)dd * npad + bi0 + i4] = yv;
    }
}

// ---------------------------------------------------------------------------
// fused: interleaved block roles.
//   i % 5 == 2 (and si < ns): strip GEMM block (bit-identical body);
//   else: zero block -- 8 full contiguous rows, warp per row (proven writer).
// Grid = 5 * ns blocks; zero slots = 4*ns = npad/8 >= ceil(N/8).
// ---------------------------------------------------------------------------
__global__ __launch_bounds__(256, 2) void fused_kernel(float* __restrict__ out,
                                                       int N, int npad,
                                                       int ns) {
    const int i = blockIdx.x;
    const int t = threadIdx.x;

    if ((i % 5) == 2) {
        const int si = (i - 2) / 5;
        if (si >= ns) return;
        const int bn = (si & 1) * 128;
        const int bm = (si >> 1) * 64;

        extern __shared__ float sm[];
        float* Asf = sm;           // [k][r] 128 x 64
        float* Bsf = sm + 8192;    // [k][r] 128 x 128

        const int tx = t & 15, ty = t >> 4;

        {
            const float4* Xv = reinterpret_cast<const float4*>(g_Xt);
            const float4* Yv = reinterpret_cast<const float4*>(g_Yt);
            uint32_t As_s = (uint32_t)__cvta_generic_to_shared(Asf);
            uint32_t Bs_s = (uint32_t)__cvta_generic_to_shared(Bsf);
            const int np4 = npad >> 2;
            const int bm4 = bm >> 2, bn4 = bn >> 2;
#pragma unroll
            for (int e = 0; e < 8; e++) {
                int q = e * 256 + t;
                int k = q >> 4;
                int r4 = q & 15;
                cp_async16(As_s + q * 16, &Xv[(size_t)k * np4 + bm4 + r4]);
            }
#pragma unroll
            for (int e = 0; e < 16; e++) {
                int q = e * 256 + t;
                int k = q >> 5;
                int r4 = q & 31;
                cp_async16(Bs_s + q * 16, &Yv[(size_t)k * np4 + bn4 + r4]);
            }
            asm volatile("cp.async.commit_group;");
            asm volatile("cp.async.wait_group 0;");
        }
        __syncthreads();

        float acc[4][8];
#pragma unroll
        for (int a = 0; a < 4; a++)
#pragma unroll
            for (int b = 0; b < 8; b++) acc[a][b] = 0.0f;

#pragma unroll 4
        for (int k = 0; k < 128; k++) {
            const float* ak = Asf + k * 64;
            const float* bk = Bsf + k * 128;
            float4 a0 = *(const float4*)(ak + ty * 4);
            float4 b0 = *(const float4*)(bk + tx * 4);
            float4 b1 = *(const float4*)(bk + 64 + tx * 4);
            float ra[4] = {a0.x, a0.y, a0.z, a0.w};
            float rb[8] = {b0.x, b0.y, b0.z, b0.w, b1.x, b1.y, b1.z, b1.w};
#pragma unroll
            for (int a = 0; a < 4; a++)
#pragma unroll
                for (int b = 0; b < 8; b++)
                    acc[a][b] = fmaf(ra[a], rb[b], acc[a][b]);
        }

#pragma unroll
        for (int a = 0; a < 4; a++)
#pragma unroll
            for (int b = 0; b < 8; b++) acc[a][b] = tanh_xla(3.0f * acc[a][b]);

        __syncthreads();  // As/Bs dead

        unsigned* mUw = reinterpret_cast<unsigned*>(sm);  // [64][32] nibbles
        const unsigned satb = __float_as_uint(sat_val());

#pragma unroll
        for (int ii = 0; ii < 4; ii++) {
            int r = ty * 4 + ii;
#pragma unroll
            for (int q = 0; q < 2; q++) {
                unsigned nib = 0;
#pragma unroll
                for (int b = 0; b < 4; b++)
                    nib |= (__float_as_uint(acc[ii][q * 4 + b]) == satb) << b;
                mUw[r * 32 + 16 * q + tx] = nib;
            }
        }
        __syncthreads();

        {
            int r = t >> 2, ww = t & 3;
            unsigned wd = 0;
#pragma unroll
            for (int b = 0; b < 8; b++)
                wd |= mUw[r * 32 + ww * 8 + b] << (4 * b);
            g_maskS[(size_t)(bm + r) * 8 + (bn >> 5) + ww] = wd;
        }
    } else {
        // zero role: full rows [0, N)
        const int zi = i - (i + 2) / 5;  // count of strip blocks before i
        const int row = zi * 8 + (t >> 5);
        const int lane = t & 31;
        if (row >= N) return;
        float* rowp = out + (size_t)row * N;
        const int nv = N >> 2;
        const float4 z = make_float4(0.0f, 0.0f, 0.0f, 0.0f);
        for (int q = lane; q < nv; q += 32)
            reinterpret_cast<float4*>(rowp)[q] = z;
        for (int q = nv * 4 + lane; q < N; q += 32) rowp[q] = 0.0f;
    }
}

// ---------------------------------------------------------------------------
// scatter: warp per row. Scatter satval at the 20 smallest set bits of the
// strip mask into the (pre-zeroed) row. <20 bits -> fallback list.
// ---------------------------------------------------------------------------
__global__ __launch_bounds__(256) void scatter_kernel(float* __restrict__ out,
                                                      int N) {
    const int row = blockIdx.x * 8 + (threadIdx.x >> 5);
    const int lane = threadIdx.x & 31;
    if (row >= N) return;

    unsigned w = (lane < 8) ? g_maskS[(size_t)row * 8 + lane] : 0u;
    int c = __popc(w);
    int incl = c;
#pragma unroll
    for (int s = 1; s < 32; s <<= 1) {
        int o = __shfl_up_sync(0xffffffffu, incl, s);
        if (lane >= s) incl += o;
    }
    int excl = incl - c;
    int total = __shfl_sync(0xffffffffu, incl, 31);

    if (total >= 20) {
        const float sv = sat_val();
        float* rowp = out + (size_t)row * N;
        int base = excl;
        unsigned ww = w;
        while (ww && base < 20) {
            int b = __ffs(ww) - 1;
            ww &= ww - 1;
            rowp[lane * 32 + b] = sv;
            base++;
        }
    } else if (lane == 0) {
        int p = atomicAdd(&g_fb_cnt, 1);
        g_fb_list[p] = row;
    }
}

// ---------------------------------------------------------------------------
// fallback: exact full-row recompute + general top-20 (expected 0 rows).
// ---------------------------------------------------------------------------
__global__ __launch_bounds__(256) void fallback_kernel(float* __restrict__ out,
                                                       int N, int npad) {
    __shared__ float sX[128];
    __shared__ __align__(16) float srow[10016];
    __shared__ unsigned long long red[256];
    __shared__ int selIdx[20];
    __shared__ float selVal[20];

    const int t = threadIdx.x;
    const int cnt = g_fb_cnt;

    for (int ri = blockIdx.x; ri < cnt; ri += gridDim.x) {
        const int row = g_fb_list[ri];
        if (t < 128) sX[t] = g_Xt[(size_t)t * npad + row];
        __syncthreads();

        for (int j = t; j < N; j += 256) {
            float a = 0.0f;
#pragma unroll 4
            for (int k = 0; k < 128; k++)
                a = fmaf(sX[k], g_Yt[(size_t)k * npad + j], a);
            srow[j] = fmaxf(tanh_xla(3.0f * a), 0.0f);
        }
        __syncthreads();

        unsigned long long cand[20];
#pragma unroll
        for (int c = 0; c < 20; c++) cand[c] = 0ull;
        unsigned long long curMin = 0ull;
        for (int q = t; q < N; q += 256) {
            unsigned vb = __float_as_uint(srow[q]);
            if (vb == 0x80000000u) vb = 0u;
            unsigned long long key =
                ((unsigned long long)vb << 32) |
                (unsigned long long)(0xFFFFFFFFu - (unsigned)q);
            if (key > curMin) {
                bool done = false;
#pragma unroll
                for (int c = 0; c < 20; c++) {
                    if (!done && cand[c] == curMin) {
                        cand[c] = key;
                        done = true;
                    }
                }
                unsigned long long m = cand[0];
#pragma unroll
                for (int c = 1; c < 20; c++) m = (cand[c] < m) ? cand[c] : m;
                curMin = m;
            }
        }
        for (int it = 0; it < 20; it++) {
            unsigned long long m = cand[0];
#pragma unroll
            for (int c = 1; c < 20; c++) m = (cand[c] > m) ? cand[c] : m;
            red[t] = m;
            __syncthreads();
            for (int s = 128; s >= 32; s >>= 1) {
                if (t < s) {
                    unsigned long long o = red[t + s];
                    if (o > red[t]) red[t] = o;
                }
                __syncthreads();
            }
            if (t < 32) {
                unsigned long long g = red[t];
#pragma unroll
                for (int s = 16; s; s >>= 1) {
                    unsigned long long o = __shfl_xor_sync(0xffffffffu, g, s);
                    if (o > g) g = o;
                }
                if (t == 0) red[0] = g;
            }
            __syncthreads();
            unsigned long long g = red[0];
            if (t == 0) {
                if (g != 0ull) {
                    selIdx[it] =
                        (int)(0xFFFFFFFFu - (unsigned)(g & 0xFFFFFFFFull));
                    selVal[it] = __uint_as_float((unsigned)(g >> 32));
                } else {
                    selIdx[it] = 0;
                    selVal[it] = 0.0f;
                }
            }
            if (g != 0ull) {
#pragma unroll
                for (int c = 0; c < 20; c++)
                    if (cand[c] == g) cand[c] = 0ull;
            }
            __syncthreads();
        }
        if (t < 20) out[(size_t)row * N + selIdx[t]] = selVal[t];
        __syncthreads();
    }
}

// ---------------------------------------------------------------------------
extern "C" void kernel_launch(void* const* d_in, const int* in_sizes, int n_in,
                              void* d_out, int out_size) {
    const int* idx = (const int*)d_in[0];
    const float* gEmb = (const float*)d_in[1];
    const float* embW = (const float*)d_in[2];
    const float* fc1w = (const float*)d_in[3];
    const float* fc1b = (const float*)d_in[4];
    float* out = (float*)d_out;

    int N = in_sizes[0];
    int npad = ((N + 127) / 128) * 128;
    int tiles64 = npad / 64;
    int ns = 2 * tiles64;       // strip blocks
    int total = 5 * ns;         // zero slots = 4*ns = npad/8 >= ceil(N/8)

    static bool s_init = false;
    if (!s_init) {
        cudaFuncSetAttribute(fused_kernel,
                             cudaFuncAttributeMaxDynamicSharedMemorySize,
                             98304);
        cudaFuncSetAttribute(prep_kernel,
                             cudaFuncAttributeMaxDynamicSharedMemorySize,
                             PREP_SMEM_FLOATS * 4);
        s_init = true;
    }

    prep_kernel<<<npad / 64, 256, PREP_SMEM_FLOATS * 4>>>(idx, gEmb, embW,
                                                          fc1w, fc1b, N, npad);
    fused_kernel<<<total, 256, 98304>>>(out, N, npad, ns);
    scatter_kernel<<<(N + 7) / 8, 256>>>(out, N);
    fallback_kernel<<<16, 256>>>(out, N, npad);
}

// round 16
// speedup vs baseline: 1.1632x; 1.0036x over previous
#include <cuda_runtime.h>
#include <cstdint>

// ---------------------------------------------------------------------------
// local_graph_creator: adj = relu(tanh(3*(vec1@gEmb.T - gEmb@vec1.T))),
// per-row top-20 (value desc, index asc) binary mask applied.
//
// Exact-output structure (rel_err == 0.0 across rounds 1-15): each output row
// is zeros plus satval at the 20 smallest column indices whose tanh saturates
// (bits == satval). Only an exact N x 256 strip of scores is needed; rows
// with <20 saturated strip entries go to an exact full-row fallback.
//
// Round-15 framework (grid-level fusion) extended: scatter is folded into the
// fused kernel as a producer-consumer. Strip blocks are the FIRST ns bids
// (dispatch-first), write masks, fence, bump g_strip_done. Zero blocks zero
// their 8 full rows first (~60us), then poll g_strip_done==ns (long done by
// then), acquire-fence, and scatter their own rows. Bounded spin + flag-to-
// fallback escape = deadlock-free; pathological schedules degrade to the
// exact fallback path, never to wrong answers.
//
//   default stream: prep -> fused2(strip | zero+scatter) -> fallback
// ---------------------------------------------------------------------------

#define MAX_NPAD 10112
#define STRIPW 256

__device__ float g_Xt[128 * MAX_NPAD];     // [k][i]  X = [vec1 | -gEmb]
__device__ float g_Yt[128 * MAX_NPAD];     // [k][i]  Y = [gEmb  |  vec1]
__device__ unsigned g_maskS[MAX_NPAD * 8]; // strip tie bitmask (256 cols/row)
__device__ int g_fb_cnt;
__device__ int g_fb_list[MAX_NPAD];
__device__ int g_strip_done;

__device__ __forceinline__ float tanh_xla(float x) {
    const float kClamp = 7.99881172180175781f;
    float ax = fabsf(x);
    float xc = fminf(fmaxf(x, -kClamp), kClamp);
    float x2 = xc * xc;
    float p = -2.76076847742355e-16f;
    p = fmaf(x2, p, 2.00018790482477e-13f);
    p = fmaf(x2, p, -8.60467152213735e-11f);
    p = fmaf(x2, p, 5.12229709037114e-08f);
    p = fmaf(x2, p, 1.48572235717979e-05f);
    p = fmaf(x2, p, 6.37261928875436e-04f);
    p = fmaf(x2, p, 4.89352455891786e-03f);
    p = xc * p;
    float q = fmaf(x2, 1.19825839466702e-06f, 1.18534705686654e-04f);
    q = fmaf(x2, q, 2.26843463243900e-03f);
    q = fmaf(x2, q, 4.89352518554385e-03f);
    float r = p / q;
    return (ax < 0.0004f) ? x : r;
}

__device__ __forceinline__ float sat_val() { return tanh_xla(8.0f); }

__device__ __forceinline__ void cp_async16(uint32_t saddr, const void* gaddr) {
    asm volatile("cp.async.cg.shared.global [%0], [%1], 16;" ::
                 "r"(saddr), "l"(gaddr));
}

// ---------------------------------------------------------------------------
// prep: 64 rows per block. fc1_w row cached in registers, emb row via
// broadcast float4 LDS -- same k-ascending fmaf chain (bit-identical vec1).
// ---------------------------------------------------------------------------
#define PREP_SMEM_FLOATS (3 * 4160 + 64 + 64)
__global__ __launch_bounds__(256) void prep_kernel(
    const int* __restrict__ idx, const float* __restrict__ gEmb,
    const float* __restrict__ embW, const float* __restrict__ fc1w,
    const float* __restrict__ fc1b, int N, int npad) {
    extern __shared__ float ps[];
    float* wst = ps;             // [d][k] stride 65
    float* sv = ps + 4160;       // [d][il] stride 65
    float* sbuf = ps + 8320;     // [il][k] stride 64 emb; later [d][il] s65
    float* bs = ps + 12480;      // [64]
    int* sidx = (int*)(ps + 12544);  // [64]

    const int t = threadIdx.x;
    const int bi0 = blockIdx.x * 64;

    if (blockIdx.x == 0 && t == 0) {
        g_fb_cnt = 0;
        g_strip_done = 0;
    }

    if (t < 64) {
        bs[t] = fc1b[t];
        int i = bi0 + t;
        sidx[t] = (i < N) ? idx[i] : 0;
    }
    for (int e = t; e < 64 * 64; e += 256) {
        int d = e >> 6, k = e & 63;
        wst[d * 65 + k] = fc1w[e];
    }
    __syncthreads();

    // gathered emb rows, stride 64 (16B-aligned rows for float4 broadcast)
    for (int e = t; e < 64 * 64; e += 256) {
        int il = e >> 6, k = e & 63;
        int i = bi0 + il;
        sbuf[il * 64 + k] = (i < N) ? embW[(size_t)sidx[il] * 64 + k] : 0.0f;
    }
    __syncthreads();

    const int d = t & 63;
    const int rq = t >> 6;

    float wreg[64];
#pragma unroll
    for (int k = 0; k < 64; k++) wreg[k] = wst[d * 65 + k];

#pragma unroll
    for (int rr = 0; rr < 16; rr++) {
        int il = rr * 4 + rq;
        int i = bi0 + il;
        float v = 0.0f;
        if (i < N) {
            const float4* er4 =
                reinterpret_cast<const float4*>(&sbuf[il * 64]);
            float acc = 0.0f;
#pragma unroll
            for (int k4 = 0; k4 < 16; k4++) {
                float4 e4 = er4[k4];
                acc = fmaf(e4.x, wreg[k4 * 4 + 0], acc);
                acc = fmaf(e4.y, wreg[k4 * 4 + 1], acc);
                acc = fmaf(e4.z, wreg[k4 * 4 + 2], acc);
                acc = fmaf(e4.w, wreg[k4 * 4 + 3], acc);
            }
            acc += bs[d];
            v = tanh_xla(3.0f * acc);
        }
        sv[d * 65 + il] = v;
    }
    __syncthreads();

    // reuse sbuf as gEmb^T [d][il], stride 65
#pragma unroll 4
    for (int e = t; e < 64 * 64; e += 256) {
        int il = e >> 6, dd = e & 63;
        int i = bi0 + il;
        sbuf[dd * 65 + il] = (i < N) ? gEmb[(size_t)i * 64 + dd] : 0.0f;
    }
    __syncthreads();

#pragma unroll
    for (int p = 0; p < 8; p++) {
        int e = p * 256 + t;
        int dd = e >> 4;
        int i4 = (e & 15) * 4;
        float4 xv, yv;
        if (dd < 64) {
            xv.x = sv[dd * 65 + i4 + 0]; xv.y = sv[dd * 65 + i4 + 1];
            xv.z = sv[dd * 65 + i4 + 2]; xv.w = sv[dd * 65 + i4 + 3];
            yv.x = sbuf[dd * 65 + i4 + 0]; yv.y = sbuf[dd * 65 + i4 + 1];
            yv.z = sbuf[dd * 65 + i4 + 2]; yv.w = sbuf[dd * 65 + i4 + 3];
        } else {
            int dl = dd - 64;
            xv.x = -sbuf[dl * 65 + i4 + 0]; xv.y = -sbuf[dl * 65 + i4 + 1];
            xv.z = -sbuf[dl * 65 + i4 + 2]; xv.w = -sbuf[dl * 65 + i4 + 3];
            yv.x = sv[dl * 65 + i4 + 0];  yv.y = sv[dl * 65 + i4 + 1];
            yv.z = sv[dl * 65 + i4 + 2];  yv.w = sv[dl * 65 + i4 + 3];
        }
        *(float4*)&g_Xt[(size_t)dd * npad + bi0 + i4] = xv;
        *(float4*)&g_Yt[(size_t)dd * npad + bi0 + i4] = yv;
    }
}

// ---------------------------------------------------------------------------
// fused2: bids [0,ns) = strip blocks (bit-identical GEMM body -> masks ->
// fence -> g_strip_done++). bids [ns,..) = zero blocks: zero 8 full rows,
// bounded-poll g_strip_done==ns, acquire-fence, scatter own rows (or flag
// rows to the exact fallback if the spin budget expires).
// ---------------------------------------------------------------------------
__global__ __launch_bounds__(256, 2) void fused2_kernel(
    float* __restrict__ out, int N, int npad, int ns) {
    const int i = blockIdx.x;
    const int t = threadIdx.x;

    if (i < ns) {
        const int si = i;
        const int bn = (si & 1) * 128;
        const int bm = (si >> 1) * 64;

        extern __shared__ float sm[];
        float* Asf = sm;           // [k][r] 128 x 64
        float* Bsf = sm + 8192;    // [k][r] 128 x 128

        const int tx = t & 15, ty = t >> 4;

        {
            const float4* Xv = reinterpret_cast<const float4*>(g_Xt);
            const float4* Yv = reinterpret_cast<const float4*>(g_Yt);
            uint32_t As_s = (uint32_t)__cvta_generic_to_shared(Asf);
            uint32_t Bs_s = (uint32_t)__cvta_generic_to_shared(Bsf);
            const int np4 = npad >> 2;
            const int bm4 = bm >> 2, bn4 = bn >> 2;
#pragma unroll
            for (int e = 0; e < 8; e++) {
                int q = e * 256 + t;
                int k = q >> 4;
                int r4 = q & 15;
                cp_async16(As_s + q * 16, &Xv[(size_t)k * np4 + bm4 + r4]);
            }
#pragma unroll
            for (int e = 0; e < 16; e++) {
                int q = e * 256 + t;
                int k = q >> 5;
                int r4 = q & 31;
                cp_async16(Bs_s + q * 16, &Yv[(size_t)k * np4 + bn4 + r4]);
            }
            asm volatile("cp.async.commit_group;");
            asm volatile("cp.async.wait_group 0;");
        }
        __syncthreads();

        float acc[4][8];
#pragma unroll
        for (int a = 0; a < 4; a++)
#pragma unroll
            for (int b = 0; b < 8; b++) acc[a][b] = 0.0f;

#pragma unroll 4
        for (int k = 0; k < 128; k++) {
            const float* ak = Asf + k * 64;
            const float* bk = Bsf + k * 128;
            float4 a0 = *(const float4*)(ak + ty * 4);
            float4 b0 = *(const float4*)(bk + tx * 4);
            float4 b1 = *(const float4*)(bk + 64 + tx * 4);
            float ra[4] = {a0.x, a0.y, a0.z, a0.w};
            float rb[8] = {b0.x, b0.y, b0.z, b0.w, b1.x, b1.y, b1.z, b1.w};
#pragma unroll
            for (int a = 0; a < 4; a++)
#pragma unroll
                for (int b = 0; b < 8; b++)
                    acc[a][b] = fmaf(ra[a], rb[b], acc[a][b]);
        }

#pragma unroll
        for (int a = 0; a < 4; a++)
#pragma unroll
            for (int b = 0; b < 8; b++) acc[a][b] = tanh_xla(3.0f * acc[a][b]);

        __syncthreads();  // As/Bs dead

        unsigned* mUw = reinterpret_cast<unsigned*>(sm);  // [64][32] nibbles
        const unsigned satb = __float_as_uint(sat_val());

#pragma unroll
        for (int ii = 0; ii < 4; ii++) {
            int r = ty * 4 + ii;
#pragma unroll
            for (int q = 0; q < 2; q++) {
                unsigned nib = 0;
#pragma unroll
                for (int b = 0; b < 4; b++)
                    nib |= (__float_as_uint(acc[ii][q * 4 + b]) == satb) << b;
                mUw[r * 32 + 16 * q + tx] = nib;
            }
        }
        __syncthreads();

        {
            int r = t >> 2, ww = t & 3;
            unsigned wd = 0;
#pragma unroll
            for (int b = 0; b < 8; b++)
                wd |= mUw[r * 32 + ww * 8 + b] << (4 * b);
            g_maskS[(size_t)(bm + r) * 8 + (bn >> 5) + ww] = wd;
        }

        // publish: all mask writes visible before the done-increment
        __threadfence();
        __syncthreads();
        if (t == 0) atomicAdd(&g_strip_done, 1);
    } else {
        // zero + scatter role
        __shared__ int sok;
        const int zi = i - ns;
        const int row = zi * 8 + (t >> 5);
        const int lane = t & 31;

        if (row < N) {
            float* rowp = out + (size_t)row * N;
            const int nv = N >> 2;
            const float4 z = make_float4(0.0f, 0.0f, 0.0f, 0.0f);
            for (int q = lane; q < nv; q += 32)
                reinterpret_cast<float4*>(rowp)[q] = z;
            for (int q = nv * 4 + lane; q < N; q += 32) rowp[q] = 0.0f;
        }

        // bounded wait for strip completion (expected: already done)
        if (t == 0) {
            int ok = 1, spins = 0;
            while (atomicAdd(&g_strip_done, 0) < ns) {
                __nanosleep(64);
                if (++spins > (1 << 18)) { ok = 0; break; }
            }
            sok = ok;
        }
        __syncthreads();
        __threadfence();  // acquire: mask reads after observed done

        if (row < N) {
            if (sok) {
                unsigned w =
                    (lane < 8) ? g_maskS[(size_t)row * 8 + lane] : 0u;
                int c = __popc(w);
                int incl = c;
#pragma unroll
                for (int s = 1; s < 32; s <<= 1) {
                    int o = __shfl_up_sync(0xffffffffu, incl, s);
                    if (lane >= s) incl += o;
                }
                int excl = incl - c;
                int total = __shfl_sync(0xffffffffu, incl, 31);

                if (total >= 20) {
                    const float sv = sat_val();
                    float* rowp = out + (size_t)row * N;
                    int base = excl;
                    unsigned ww = w;
                    while (ww && base < 20) {
                        int b = __ffs(ww) - 1;
                        ww &= ww - 1;
                        rowp[lane * 32 + b] = sv;
                        base++;
                    }
                } else if (lane == 0) {
                    int p = atomicAdd(&g_fb_cnt, 1);
                    g_fb_list[p] = row;
                }
            } else if (lane == 0) {
                // spin budget expired (pathological schedule): exact fallback
                int p = atomicAdd(&g_fb_cnt, 1);
                g_fb_list[p] = row;
            }
        }
    }
}

// ---------------------------------------------------------------------------
// fallback: exact full-row recompute + general top-20 (expected 0 rows).
// ---------------------------------------------------------------------------
__global__ __launch_bounds__(256) void fallback_kernel(float* __restrict__ out,
                                                       int N, int npad) {
    __shared__ float sX[128];
    __shared__ __align__(16) float srow[10016];
    __shared__ unsigned long long red[256];
    __shared__ int selIdx[20];
    __shared__ float selVal[20];

    const int t = threadIdx.x;
    const int cnt = g_fb_cnt;

    for (int ri = blockIdx.x; ri < cnt; ri += gridDim.x) {
        const int row = g_fb_list[ri];
        if (t < 128) sX[t] = g_Xt[(size_t)t * npad + row];
        __syncthreads();

        for (int j = t; j < N; j += 256) {
            float a = 0.0f;
#pragma unroll 4
            for (int k = 0; k < 128; k++)
                a = fmaf(sX[k], g_Yt[(size_t)k * npad + j], a);
            srow[j] = fmaxf(tanh_xla(3.0f * a), 0.0f);
        }
        __syncthreads();

        // clear the row first (it may hold partial scatter state)
        for (int j = t; j < N; j += 256) out[(size_t)row * N + j] = 0.0f;

        unsigned long long cand[20];
#pragma unroll
        for (int c = 0; c < 20; c++) cand[c] = 0ull;
        unsigned long long curMin = 0ull;
        for (int q = t; q < N; q += 256) {
            unsigned vb = __float_as_uint(srow[q]);
            if (vb == 0x80000000u) vb = 0u;
            unsigned long long key =
                ((unsigned long long)vb << 32) |
                (unsigned long long)(0xFFFFFFFFu - (unsigned)q);
            if (key > curMin) {
                bool done = false;
#pragma unroll
                for (int c = 0; c < 20; c++) {
                    if (!done && cand[c] == curMin) {
                        cand[c] = key;
                        done = true;
                    }
                }
                unsigned long long m = cand[0];
#pragma unroll
                for (int c = 1; c < 20; c++) m = (cand[c] < m) ? cand[c] : m;
                curMin = m;
            }
        }
        for (int it = 0; it < 20; it++) {
            unsigned long long m = cand[0];
#pragma unroll
            for (int c = 1; c < 20; c++) m = (cand[c] > m) ? cand[c] : m;
            red[t] = m;
            __syncthreads();
            for (int s = 128; s >= 32; s >>= 1) {
                if (t < s) {
                    unsigned long long o = red[t + s];
                    if (o > red[t]) red[t] = o;
                }
                __syncthreads();
            }
            if (t < 32) {
                unsigned long long g = red[t];
#pragma unroll
                for (int s = 16; s; s >>= 1) {
                    unsigned long long o = __shfl_xor_sync(0xffffffffu, g, s);
                    if (o > g) g = o;
                }
                if (t == 0) red[0] = g;
            }
            __syncthreads();
            unsigned long long g = red[0];
            if (t == 0) {
                if (g != 0ull) {
                    selIdx[it] =
                        (int)(0xFFFFFFFFu - (unsigned)(g & 0xFFFFFFFFull));
                    selVal[it] = __uint_as_float((unsigned)(g >> 32));
                } else {
                    selIdx[it] = 0;
                    selVal[it] = 0.0f;
                }
            }
            if (g != 0ull) {
#pragma unroll
                for (int c = 0; c < 20; c++)
                    if (cand[c] == g) cand[c] = 0ull;
            }
            __syncthreads();
        }
        if (t < 20) out[(size_t)row * N + selIdx[t]] = selVal[t];
        __syncthreads();
    }
}

// ---------------------------------------------------------------------------
extern "C" void kernel_launch(void* const* d_in, const int* in_sizes, int n_in,
                              void* d_out, int out_size) {
    const int* idx = (const int*)d_in[0];
    const float* gEmb = (const float*)d_in[1];
    const float* embW = (const float*)d_in[2];
    const float* fc1w = (const float*)d_in[3];
    const float* fc1b = (const float*)d_in[4];
    float* out = (float*)d_out;

    int N = in_sizes[0];
    int npad = ((N + 127) / 128) * 128;
    int tiles64 = npad / 64;
    int ns = 2 * tiles64;          // strip blocks (first bids)
    int nz = (N + 7) / 8;          // zero+scatter blocks

    static bool s_init = false;
    if (!s_init) {
        cudaFuncSetAttribute(fused2_kernel,
                             cudaFuncAttributeMaxDynamicSharedMemorySize,
                             98304);
        cudaFuncSetAttribute(prep_kernel,
                             cudaFuncAttributeMaxDynamicSharedMemorySize,
                             PREP_SMEM_FLOATS * 4);
        s_init = true;
    }

    prep_kernel<<<npad / 64, 256, PREP_SMEM_FLOATS * 4>>>(idx, gEmb, embW,
                                                          fc1w, fc1b, N, npad);
    fused2_kernel<<<ns + nz, 256, 98304>>>(out, N, npad, ns);
    fallback_kernel<<<16, 256>>>(out, N, npad);
}